// round 16
// baseline (speedup 1.0000x reference)
#include <cuda_runtime.h>
#include <cuda_fp16.h>
#include <cstdint>

#define N_NODES 16384
#define IN_DIM  512
#define OUT_DIM 256

// ---------------------------------------------------------------------------
// Device scratch (no runtime allocation allowed)
// ---------------------------------------------------------------------------
__device__ float  g_dinv[N_NODES];                          // 64 KB
__device__ float  g_feat[(size_t)N_NODES * OUT_DIM];        // 16 MB: g fp32 (self-loop term)
__device__ __half g_g16T[(size_t)OUT_DIM * N_NODES];        // 8 MB:  g^T fp16 (B operand)

// ---------------------------------------------------------------------------
// Helpers
// ---------------------------------------------------------------------------
__device__ __forceinline__ unsigned smem_u32(const void* p) {
    unsigned r;
    asm("{ .reg .u64 t; cvta.to.shared.u64 t, %1; cvt.u32.u64 %0, t; }"
        : "=r"(r) : "l"(p));
    return r;
}

#define CP_ASYNC16(dst, src) \
    asm volatile("cp.async.cg.shared.global [%0], [%1], 16;\n" :: "r"(dst), "l"(src))
#define CP_COMMIT() asm volatile("cp.async.commit_group;\n" ::: "memory")
#define CP_WAIT1()  asm volatile("cp.async.wait_group 1;\n" ::: "memory")
#define CP_WAIT2()  asm volatile("cp.async.wait_group 2;\n" ::: "memory")

#define LDSM_X4(r0, r1, r2, r3, addr) \
    asm volatile("ldmatrix.sync.aligned.m8n8.x4.shared.b16 {%0,%1,%2,%3}, [%4];" \
                 : "=r"(r0), "=r"(r1), "=r"(r2), "=r"(r3) : "r"(addr))

__device__ __forceinline__ void mma_f16(float& d0, float& d1, float& d2, float& d3,
                                        unsigned a0, unsigned a1, unsigned a2, unsigned a3,
                                        unsigned b0, unsigned b1) {
    asm volatile(
        "mma.sync.aligned.m16n8k16.row.col.f32.f16.f16.f32 "
        "{%0,%1,%2,%3}, {%4,%5,%6,%7}, {%8,%9}, {%0,%1,%2,%3};\n"
        : "+f"(d0), "+f"(d1), "+f"(d2), "+f"(d3)
        : "r"(a0), "r"(a1), "r"(a2), "r"(a3), "r"(b0), "r"(b1));
}

__device__ __forceinline__ unsigned h2_bits(__half2 h) {
    return *reinterpret_cast<unsigned*>(&h);
}

// ---------------------------------------------------------------------------
// Kernel 1: d_inv_sqrt[i] = rsqrt(1 + sum_j A[i,j])   (pure: back to HBM roofline)
// ---------------------------------------------------------------------------
__global__ void rowsum_kernel(const float* __restrict__ A) {
    const int row = blockIdx.x;
    const float4* a = reinterpret_cast<const float4*>(A + (size_t)row * N_NODES);
    float s = 0.f;
    for (int j = threadIdx.x; j < N_NODES / 4; j += blockDim.x) {
        float4 v = a[j];
        s += (v.x + v.y) + (v.z + v.w);
    }
    __shared__ float red[8];
    #pragma unroll
    for (int o = 16; o > 0; o >>= 1) s += __shfl_down_sync(0xffffffffu, s, o);
    if ((threadIdx.x & 31) == 0) red[threadIdx.x >> 5] = s;
    __syncthreads();
    if (threadIdx.x < 8) {
        s = red[threadIdx.x];
        #pragma unroll
        for (int o = 4; o > 0; o >>= 1) s += __shfl_down_sync(0xffu, s, o);
        if (threadIdx.x == 0) g_dinv[row] = rsqrtf(s + 1.0f);
    }
}

// ---------------------------------------------------------------------------
// Kernel 2: g[m,n] = d[m]*(x[m,:]@W[n,:] + b[n])
// Writes g_feat (m-major fp32) and g_g16T (n-major fp16, RN).
// ---------------------------------------------------------------------------
__global__ void linear_kernel(const float* __restrict__ x,
                              const float* __restrict__ W,
                              const float* __restrict__ bias) {
    const int BM = 64, BN = 64, BK = 16;
    __shared__ float Xs[BK][BM + 4];
    __shared__ float Ws[BK][BN + 4];

    const int m0 = blockIdx.y * BM;
    const int n0 = blockIdx.x * BN;
    const int tid = threadIdx.x;
    const int tx = tid & 15;
    const int ty = tid >> 4;

    float acc[4][4] = {};

    const int lr = tid >> 2;
    const int lc = (tid & 3) * 4;

    for (int kt = 0; kt < IN_DIM; kt += BK) {
        float4 v = *reinterpret_cast<const float4*>(x + (size_t)(m0 + lr) * IN_DIM + kt + lc);
        Xs[lc + 0][lr] = v.x; Xs[lc + 1][lr] = v.y;
        Xs[lc + 2][lr] = v.z; Xs[lc + 3][lr] = v.w;
        float4 w = *reinterpret_cast<const float4*>(W + (size_t)(n0 + lr) * IN_DIM + kt + lc);
        Ws[lc + 0][lr] = w.x; Ws[lc + 1][lr] = w.y;
        Ws[lc + 2][lr] = w.z; Ws[lc + 3][lr] = w.w;
        __syncthreads();

        #pragma unroll
        for (int k = 0; k < BK; k++) {
            float af[4], bf[4];
            #pragma unroll
            for (int i = 0; i < 4; i++) af[i] = Xs[k][ty * 4 + i];
            #pragma unroll
            for (int j = 0; j < 4; j++) bf[j] = Ws[k][tx * 4 + j];
            #pragma unroll
            for (int i = 0; i < 4; i++)
                #pragma unroll
                for (int j = 0; j < 4; j++)
                    acc[i][j] = fmaf(af[i], bf[j], acc[i][j]);
        }
        __syncthreads();
    }

    float dv[4];
    #pragma unroll
    for (int i = 0; i < 4; i++) dv[i] = g_dinv[m0 + ty * 4 + i];

    #pragma unroll
    for (int i = 0; i < 4; i++) {
        const int gm = m0 + ty * 4 + i;
        float4 o;
        o.x = dv[i] * (acc[i][0] + bias[n0 + tx * 4 + 0]);
        o.y = dv[i] * (acc[i][1] + bias[n0 + tx * 4 + 1]);
        o.z = dv[i] * (acc[i][2] + bias[n0 + tx * 4 + 2]);
        o.w = dv[i] * (acc[i][3] + bias[n0 + tx * 4 + 3]);
        *reinterpret_cast<float4*>(g_feat + (size_t)gm * OUT_DIM + n0 + tx * 4) = o;
    }
    #pragma unroll
    for (int j = 0; j < 4; j++) {
        const int gn = n0 + tx * 4 + j;
        float f[4];
        #pragma unroll
        for (int i = 0; i < 4; i++)
            f[i] = dv[i] * (acc[i][j] + bias[gn]);
        __half2 h0 = __floats2half2_rn(f[0], f[1]);
        __half2 h1 = __floats2half2_rn(f[2], f[3]);
        *reinterpret_cast<uint2*>(g_g16T + (size_t)gn * N_NODES + m0 + ty * 4) =
            make_uint2(h2_bits(h0), h2_bits(h1));
    }
}

// ---------------------------------------------------------------------------
// Kernel 3 (persistent): out[m,:] = d[m]*( A[m,:] @ g + g[m,:] ), fp16 HMMA.
// 148 CTAs; CTA e owns m16 strips [e*256/37, (e+1)*256/37) of 1024 (6 or 7).
// 512 threads = 16 warps, warp w owns N-columns [16w, 16w+16).
// Per k32 chunk: stage fp32 A rows (contiguous: ns*16) + fp16 B (256x32);
// convert A to fp16 into a double-buffered SMEM tile; ldmatrix + mma.m16n8k16.
// 4-stage cp.async ring, wait_group 1, ONE barrier per chunk:
//   wait -> bar -> prefetch(c+3) -> convert(c+1) -> MMA(c).
// ---------------------------------------------------------------------------
#define NCH      512                      // k chunks of 32
#define RSA      160                      // fp32 A stage row stride (32 data + 8 pad floats)
#define A32B     (112 * RSA)              // 17920 B (max 7 strips)
#define RSB      80                       // fp16 row stride (32 data + 8 pad halves)
#define B_B      (256 * RSB)              // 20480 B
#define STG_B    (A32B + B_B)             // 38400 B
#define SM_A16   (4 * STG_B)              // 153600: A16 double buffer offset
#define A16B     (112 * RSB)              // 8960 B per buffer
#define AGG_SMEM (SM_A16 + 2 * A16B)      // 171520 B

__global__ void __launch_bounds__(512, 1)
agg_kernel(const float* __restrict__ A, float* __restrict__ out) {
    extern __shared__ char smc[];
    const unsigned sm0 = smem_u32(smc);
    const int tid  = threadIdx.x;
    const int wid  = tid >> 5;
    const int lane = tid & 31;
    const int gid  = lane >> 2;
    const int tig  = lane & 3;
    const int q    = lane >> 3;     // ldmatrix quad
    const int w8   = lane & 7;

    const int e  = blockIdx.x;
    const int s0 = (e * 256) / 37;          // first m16 strip
    const int ns = ((e + 1) * 256) / 37 - s0;  // 6 or 7
    const int nrows = ns * 16;
    const int grow0 = s0 * 16;

    // ---- cp.async geometry ----
    const int  atr  = tid >> 2;                    // A tile row 0..127 (use < nrows)
    const int  aseg = (tid & 3) * 32;              // 32B segment (2x16B)
    const bool aAct = atr < nrows;
    const char* agp = reinterpret_cast<const char*>(A) +
                      ((size_t)(grow0 + atr)) * (N_NODES * 4) + aseg;
    const unsigned aDst = sm0 + atr * RSA + aseg;

    const int  brow = tid >> 1;                    // 0..255
    const int  boff = (tid & 1) * 32;
    const char* bgp = reinterpret_cast<const char*>(g_g16T) +
                      (size_t)brow * (N_NODES * 2) + boff;
    const unsigned bDst = sm0 + A32B + brow * RSB + boff;

    // ---- ldmatrix lane offsets ----
    // A frag (within strip): (rowblk=q&1, k-half=q>>1)
    const unsigned aLane = (unsigned)(((q & 1) * 8 + w8) * RSB + (q >> 1) * 16);
    // B frag (warp n-slice 16): (n-rowblk=q>>1, k-half=q&1)
    const unsigned bLane = (unsigned)((wid * 16 + (q >> 1) * 8 + w8) * RSB + (q & 1) * 16);

    const int nf4 = ns * 128;   // float4 count to convert per chunk (nrows*8)

    // ---- prologue: chunks 0,1,2 into stages 0,1,2 ----
    #pragma unroll
    for (int p = 0; p < 3; p++) {
        if (aAct) {
            CP_ASYNC16(aDst + p * STG_B,      agp + (size_t)p * 128);
            CP_ASYNC16(aDst + p * STG_B + 16, agp + (size_t)p * 128 + 16);
        }
        CP_ASYNC16(bDst + p * STG_B,      bgp + (size_t)p * 64);
        CP_ASYNC16(bDst + p * STG_B + 16, bgp + (size_t)p * 64 + 16);
        CP_COMMIT();
    }
    CP_WAIT2();                 // chunk 0 staged
    __syncthreads();
    {   // convert chunk 0 -> A16 buf 0
        const char* b32 = smc;                      // stage 0
        char* b16 = smc + SM_A16;                   // buf 0
        for (int idx = tid; idx < nf4; idx += 512) {
            const int r = idx >> 3, qq = idx & 7;
            float4 v = *reinterpret_cast<const float4*>(b32 + r * RSA + qq * 16);
            __half2 h0 = __floats2half2_rn(v.x, v.y);
            __half2 h1 = __floats2half2_rn(v.z, v.w);
            *reinterpret_cast<uint2*>(b16 + r * RSB + qq * 8) =
                make_uint2(h2_bits(h0), h2_bits(h1));
        }
    }

    float d[7][2][4] = {};

    for (int c = 0; c < NCH; c++) {
        CP_WAIT1();              // chunk c+1 staged (only c+2 pending)
        __syncthreads();         // all warps done chunk c-1 (stage & A16-buf WAR safe)

        // ---- prefetch chunk c+3 into stage (c+3)&3 ----
        const int cp = c + 3;
        if (cp < NCH) {
            const unsigned so = (unsigned)(cp & 3) * STG_B;
            if (aAct) {
                CP_ASYNC16(aDst + so,      agp + (size_t)cp * 128);
                CP_ASYNC16(aDst + so + 16, agp + (size_t)cp * 128 + 16);
            }
            CP_ASYNC16(bDst + so,      bgp + (size_t)cp * 64);
            CP_ASYNC16(bDst + so + 16, bgp + (size_t)cp * 64 + 16);
        }
        CP_COMMIT();             // empty group in tail keeps wait counts exact

        // ---- convert chunk c+1 into A16 buf (c+1)&1 ----
        if (c + 1 < NCH) {
            const char* b32 = smc + (size_t)((c + 1) & 3) * STG_B;
            char* b16 = smc + SM_A16 + (size_t)((c + 1) & 1) * A16B;
            for (int idx = tid; idx < nf4; idx += 512) {
                const int r = idx >> 3, qq = idx & 7;
                float4 v = *reinterpret_cast<const float4*>(b32 + r * RSA + qq * 16);
                __half2 h0 = __floats2half2_rn(v.x, v.y);
                __half2 h1 = __floats2half2_rn(v.z, v.w);
                *reinterpret_cast<uint2*>(b16 + r * RSB + qq * 8) =
                    make_uint2(h2_bits(h0), h2_bits(h1));
            }
        }

        // ---- MMA on chunk c ----
        const unsigned bBase = sm0 + (unsigned)(c & 3) * STG_B + A32B + bLane;
        const unsigned aBase = sm0 + SM_A16 + (unsigned)(c & 1) * A16B + aLane;

        #pragma unroll
        for (int ks = 0; ks < 2; ks++) {
            const unsigned ko = (unsigned)ks * 32;
            unsigned bb0, bb1, bb2, bb3;
            LDSM_X4(bb0, bb1, bb2, bb3, bBase + ko);
            #pragma unroll
            for (int st = 0; st < 7; st++) {
                if (st < ns) {
                    unsigned a0, a1, a2, a3;
                    LDSM_X4(a0, a1, a2, a3, aBase + st * (16 * RSB) + ko);
                    mma_f16(d[st][0][0], d[st][0][1], d[st][0][2], d[st][0][3],
                            a0, a1, a2, a3, bb0, bb1);
                    mma_f16(d[st][1][0], d[st][1][1], d[st][1][2], d[st][1][3],
                            a0, a1, a2, a3, bb2, bb3);
                }
            }
        }
    }

    // ---- epilogue: out[m,n] = d[m]*(acc + g[m,n]) ----
    #pragma unroll
    for (int st = 0; st < 7; st++) {
        if (st < ns) {
            const int m = grow0 + st * 16 + gid;       // rows m and m+8
            const float dm0 = g_dinv[m];
            const float dm1 = g_dinv[m + 8];
            const float* gf0 = g_feat + (size_t)m * OUT_DIM;
            const float* gf1 = gf0 + (size_t)8 * OUT_DIM;
            float* op0 = out + (size_t)m * OUT_DIM;
            float* op1 = op0 + (size_t)8 * OUT_DIM;
            #pragma unroll
            for (int nt = 0; nt < 2; nt++) {
                const int n = wid * 16 + nt * 8 + 2 * tig;
                float2 gv0 = *reinterpret_cast<const float2*>(gf0 + n);
                float2 gv1 = *reinterpret_cast<const float2*>(gf1 + n);
                float2 o0, o1;
                o0.x = dm0 * (d[st][nt][0] + gv0.x);
                o0.y = dm0 * (d[st][nt][1] + gv0.y);
                o1.x = dm1 * (d[st][nt][2] + gv1.x);
                o1.y = dm1 * (d[st][nt][3] + gv1.y);
                *reinterpret_cast<float2*>(op0 + n) = o0;
                *reinterpret_cast<float2*>(op1 + n) = o1;
            }
        }
    }
}

// ---------------------------------------------------------------------------
extern "C" void kernel_launch(void* const* d_in, const int* in_sizes, int n_in,
                              void* d_out, int out_size) {
    const float* x = (const float*)d_in[0];   // [16384, 512]
    const float* A = (const float*)d_in[1];   // [16384, 16384]
    const float* W = (const float*)d_in[2];   // [256, 512]
    const float* b = (const float*)d_in[3];   // [256]
    float* out = (float*)d_out;               // [16384, 256]

    cudaFuncSetAttribute(agg_kernel, cudaFuncAttributeMaxDynamicSharedMemorySize, AGG_SMEM);

    rowsum_kernel<<<N_NODES, 256>>>(A);
    linear_kernel<<<dim3(OUT_DIM / 64, N_NODES / 64), 256>>>(x, W, b);
    agg_kernel<<<148, 512, AGG_SMEM>>>(A, out);
}

// round 17
// speedup vs baseline: 1.0321x; 1.0321x over previous
#include <cuda_runtime.h>
#include <cuda_fp16.h>
#include <cstdint>

#define N_NODES 16384
#define IN_DIM  512
#define OUT_DIM 256

// ---------------------------------------------------------------------------
// Device scratch (no runtime allocation allowed)
// ---------------------------------------------------------------------------
__device__ float  g_dinv[N_NODES];                          // 64 KB
__device__ float  g_feat[(size_t)N_NODES * OUT_DIM];        // 16 MB: h = xW^T+b (fp32, UNscaled)
__device__ __half g_h16T[(size_t)OUT_DIM * N_NODES];        // 8 MB:  h^T fp16 (unscaled)
__device__ __half g_g16T[(size_t)OUT_DIM * N_NODES];        // 8 MB:  (h^T * d_j) fp16 = B operand
__device__ __half g_A16[(size_t)N_NODES * N_NODES];         // 512 MB: A fp16

// ---------------------------------------------------------------------------
// Helpers
// ---------------------------------------------------------------------------
__device__ __forceinline__ unsigned smem_u32(const void* p) {
    unsigned r;
    asm("{ .reg .u64 t; cvta.to.shared.u64 t, %1; cvt.u32.u64 %0, t; }"
        : "=r"(r) : "l"(p));
    return r;
}

#define CP_ASYNC16(dst, src) \
    asm volatile("cp.async.cg.shared.global [%0], [%1], 16;\n" :: "r"(dst), "l"(src))
#define CP_COMMIT() asm volatile("cp.async.commit_group;\n" ::: "memory")
#define CP_WAIT2()  asm volatile("cp.async.wait_group 2;\n" ::: "memory")

#define LDSM_X4(r0, r1, r2, r3, addr) \
    asm volatile("ldmatrix.sync.aligned.m8n8.x4.shared.b16 {%0,%1,%2,%3}, [%4];" \
                 : "=r"(r0), "=r"(r1), "=r"(r2), "=r"(r3) : "r"(addr))

__device__ __forceinline__ void mma_f16(float& d0, float& d1, float& d2, float& d3,
                                        unsigned a0, unsigned a1, unsigned a2, unsigned a3,
                                        unsigned b0, unsigned b1) {
    asm volatile(
        "mma.sync.aligned.m16n8k16.row.col.f32.f16.f16.f32 "
        "{%0,%1,%2,%3}, {%4,%5,%6,%7}, {%8,%9}, {%0,%1,%2,%3};\n"
        : "+f"(d0), "+f"(d1), "+f"(d2), "+f"(d3)
        : "r"(a0), "r"(a1), "r"(a2), "r"(a3), "r"(b0), "r"(b1));
}

__device__ __forceinline__ unsigned h2_bits(__half2 h) {
    return *reinterpret_cast<unsigned*>(&h);
}

// ---------------------------------------------------------------------------
// Kernel 1 (merged prep): blocks [0,1024): h = xW^T + b (independent of d);
//                         blocks [1024, 1024+16384): rowsum + A16 convert.
// Linear blocks are first so their FMA work overlaps the long A stream.
// ---------------------------------------------------------------------------
#define LIN_BLOCKS 1024

__global__ void prep_kernel(const float* __restrict__ A,
                            const float* __restrict__ x,
                            const float* __restrict__ W,
                            const float* __restrict__ bias) {
    __shared__ float Xs[16][68];
    __shared__ float Ws[16][68];
    __shared__ float red[8];

    const int tid = threadIdx.x;

    if (blockIdx.x >= LIN_BLOCKS) {
        // ---------------- rowsum + A16 ----------------
        const int row = blockIdx.x - LIN_BLOCKS;
        const float4* a = reinterpret_cast<const float4*>(A + (size_t)row * N_NODES);
        uint2* a16 = reinterpret_cast<uint2*>(g_A16 + (size_t)row * N_NODES);
        float s = 0.f;
        for (int j = tid; j < N_NODES / 4; j += blockDim.x) {
            float4 v = a[j];
            s += (v.x + v.y) + (v.z + v.w);
            __half2 h0 = __floats2half2_rn(v.x, v.y);
            __half2 h1 = __floats2half2_rn(v.z, v.w);
            a16[j] = make_uint2(h2_bits(h0), h2_bits(h1));
        }
        #pragma unroll
        for (int o = 16; o > 0; o >>= 1) s += __shfl_down_sync(0xffffffffu, s, o);
        if ((tid & 31) == 0) red[tid >> 5] = s;
        __syncthreads();
        if (tid < 8) {
            s = red[tid];
            #pragma unroll
            for (int o = 4; o > 0; o >>= 1) s += __shfl_down_sync(0xffu, s, o);
            if (tid == 0) g_dinv[row] = rsqrtf(s + 1.0f);
        }
        return;
    }

    // ---------------- linear: h = xW^T + b (no d scaling) ----------------
    const int BK = 16;
    const int m0 = (blockIdx.x >> 2) * 64;
    const int n0 = (blockIdx.x & 3) * 64;
    const int tx = tid & 15;
    const int ty = tid >> 4;

    float acc[4][4] = {};

    const int lr = tid >> 2;
    const int lc = (tid & 3) * 4;

    for (int kt = 0; kt < IN_DIM; kt += BK) {
        float4 v = *reinterpret_cast<const float4*>(x + (size_t)(m0 + lr) * IN_DIM + kt + lc);
        Xs[lc + 0][lr] = v.x; Xs[lc + 1][lr] = v.y;
        Xs[lc + 2][lr] = v.z; Xs[lc + 3][lr] = v.w;
        float4 w = *reinterpret_cast<const float4*>(W + (size_t)(n0 + lr) * IN_DIM + kt + lc);
        Ws[lc + 0][lr] = w.x; Ws[lc + 1][lr] = w.y;
        Ws[lc + 2][lr] = w.z; Ws[lc + 3][lr] = w.w;
        __syncthreads();

        #pragma unroll
        for (int k = 0; k < BK; k++) {
            float af[4], bf[4];
            #pragma unroll
            for (int i = 0; i < 4; i++) af[i] = Xs[k][ty * 4 + i];
            #pragma unroll
            for (int j = 0; j < 4; j++) bf[j] = Ws[k][tx * 4 + j];
            #pragma unroll
            for (int i = 0; i < 4; i++)
                #pragma unroll
                for (int j = 0; j < 4; j++)
                    acc[i][j] = fmaf(af[i], bf[j], acc[i][j]);
        }
        __syncthreads();
    }

    // m-major fp32 h rows
    #pragma unroll
    for (int i = 0; i < 4; i++) {
        const int gm = m0 + ty * 4 + i;
        float4 o;
        o.x = acc[i][0] + bias[n0 + tx * 4 + 0];
        o.y = acc[i][1] + bias[n0 + tx * 4 + 1];
        o.z = acc[i][2] + bias[n0 + tx * 4 + 2];
        o.w = acc[i][3] + bias[n0 + tx * 4 + 3];
        *reinterpret_cast<float4*>(g_feat + (size_t)gm * OUT_DIM + n0 + tx * 4) = o;
    }
    // n-major fp16 h rows (unscaled)
    #pragma unroll
    for (int j = 0; j < 4; j++) {
        const int gn = n0 + tx * 4 + j;
        const float bj = bias[gn];
        __half2 h0 = __floats2half2_rn(acc[0][j] + bj, acc[1][j] + bj);
        __half2 h1 = __floats2half2_rn(acc[2][j] + bj, acc[3][j] + bj);
        *reinterpret_cast<uint2*>(g_h16T + (size_t)gn * N_NODES + m0 + ty * 4) =
            make_uint2(h2_bits(h0), h2_bits(h1));
    }
}

// ---------------------------------------------------------------------------
// Kernel 2 (tiny): g16T[n][j] = h16T[n][j] * d[j]  (separate dst: replay-safe)
// ---------------------------------------------------------------------------
__global__ void scaleB_kernel() {
    const int idx = blockIdx.x * blockDim.x + threadIdx.x;   // 0 .. 4M/8-1
    const int n  = idx >> 11;                 // 16384/8 = 2048 uint4 per row
    const int j0 = (idx & 2047) * 8;
    const size_t off = (size_t)n * N_NODES + j0;

    uint4 v = *reinterpret_cast<const uint4*>(g_h16T + off);
    float4 d0 = *reinterpret_cast<const float4*>(g_dinv + j0);
    float4 d1 = *reinterpret_cast<const float4*>(g_dinv + j0 + 4);

    unsigned r[4];
    const unsigned* vp = &v.x;
    const float dd[8] = {d0.x, d0.y, d0.z, d0.w, d1.x, d1.y, d1.z, d1.w};
    #pragma unroll
    for (int k = 0; k < 4; k++) {
        __half2 h = *reinterpret_cast<const __half2*>(&vp[k]);
        float2 f = __half22float2(h);
        r[k] = h2_bits(__floats2half2_rn(f.x * dd[2*k], f.y * dd[2*k+1]));
    }
    *reinterpret_cast<uint4*>(g_g16T + off) = make_uint4(r[0], r[1], r[2], r[3]);
}

// ---------------------------------------------------------------------------
// Kernel 3 (persistent): out[m,:] = d_m * (A[m,:] @ g) + d_m^2 * h[m,:]
// 148 CTAs; CTA e owns m16 strips [e*256/37,(e+1)*256/37) (6 or 7 of 1024).
// 512 threads = 16 warps; warp w owns N cols [16w,16w+16).
// fp16 A16 + B staged via 4-stage cp.async ring (29.4 KB/stage), wait_group 2,
// ONE barrier per chunk: wait -> bar -> prefetch(c+3) -> MMA(c). No conversion.
// ---------------------------------------------------------------------------
#define NCH      512                      // k chunks of 32
#define RSB      80                       // fp16 row stride bytes (64 data + 16 pad)
#define A16B     (112 * RSB)              // 8960 B (max 7 strips)
#define B_B      (256 * RSB)              // 20480 B
#define STG_B    (A16B + B_B)             // 29440 B
#define NSTG     4
#define AGG_SMEM (NSTG * STG_B)           // 117760 B

__global__ void __launch_bounds__(512, 1)
agg_kernel(float* __restrict__ out) {
    extern __shared__ char smc[];
    const unsigned sm0 = smem_u32(smc);
    const int tid  = threadIdx.x;
    const int wid  = tid >> 5;
    const int lane = tid & 31;
    const int gid  = lane >> 2;
    const int tig  = lane & 3;
    const int q    = lane >> 3;     // ldmatrix quad
    const int w8   = lane & 7;

    const int e  = blockIdx.x;
    const int s0 = (e * 256) / 37;               // first m16 strip
    const int ns = ((e + 1) * 256) / 37 - s0;    // 6 or 7
    const int nrows = ns * 16;
    const int grow0 = s0 * 16;

    // ---- cp.async geometry ----
    // A16: nrows x 64B per chunk. thread t<448: row t>>2, 16B seg (t&3).
    const int  atr  = tid >> 2;
    const int  aseg = (tid & 3) * 16;
    const bool aAct = (atr < nrows) && ((tid & 3) < 4) && (tid < 448);
    const char* agp = reinterpret_cast<const char*>(g_A16) +
                      ((size_t)(grow0 + atr)) * (N_NODES * 2) + aseg;
    const unsigned aDst = sm0 + atr * RSB + aseg;

    // B: 256 rows x 64B per chunk. thread t: row t>>1, 32B half (t&1) = 2x16B.
    const int  brow = tid >> 1;
    const int  boff = (tid & 1) * 32;
    const char* bgp = reinterpret_cast<const char*>(g_g16T) +
                      (size_t)brow * (N_NODES * 2) + boff;
    const unsigned bDst = sm0 + A16B + brow * RSB + boff;

    // ---- ldmatrix lane offsets ----
    const unsigned aLane = (unsigned)(((q & 1) * 8 + w8) * RSB + (q >> 1) * 16);
    const unsigned bLane = (unsigned)((wid * 16 + (q >> 1) * 8 + w8) * RSB + (q & 1) * 16);

    // ---- prologue: chunks 0,1,2 into stages 0,1,2 ----
    #pragma unroll
    for (int p = 0; p < 3; p++) {
        if (aAct) CP_ASYNC16(aDst + p * STG_B, agp + (size_t)p * 64);
        CP_ASYNC16(bDst + p * STG_B,      bgp + (size_t)p * 64);
        CP_ASYNC16(bDst + p * STG_B + 16, bgp + (size_t)p * 64 + 16);
        CP_COMMIT();
    }

    float d[7][2][4] = {};

    for (int c = 0; c < NCH; c++) {
        CP_WAIT2();              // chunk c staged (<=2 groups pending)
        __syncthreads();         // readers of chunk c-1 done => stage (c+3)&3 WAR safe

        // ---- prefetch chunk c+3 into stage (c+3)&3 ----
        const int cp = c + 3;
        if (cp < NCH) {
            const unsigned so = (unsigned)(cp & 3) * STG_B;
            if (aAct) CP_ASYNC16(aDst + so, agp + (size_t)cp * 64);
            CP_ASYNC16(bDst + so,      bgp + (size_t)cp * 64);
            CP_ASYNC16(bDst + so + 16, bgp + (size_t)cp * 64 + 16);
        }
        CP_COMMIT();             // empty group in tail keeps wait counts exact

        // ---- MMA on chunk c ----
        const unsigned st0 = sm0 + (unsigned)(c & 3) * STG_B;
        const unsigned aBase = st0 + aLane;
        const unsigned bBase = st0 + A16B + bLane;

        #pragma unroll
        for (int ks = 0; ks < 2; ks++) {
            const unsigned ko = (unsigned)ks * 32;
            unsigned bb0, bb1, bb2, bb3;
            LDSM_X4(bb0, bb1, bb2, bb3, bBase + ko);
            #pragma unroll
            for (int st = 0; st < 7; st++) {
                if (st < ns) {
                    unsigned a0, a1, a2, a3;
                    LDSM_X4(a0, a1, a2, a3, aBase + st * (16 * RSB) + ko);
                    mma_f16(d[st][0][0], d[st][0][1], d[st][0][2], d[st][0][3],
                            a0, a1, a2, a3, bb0, bb1);
                    mma_f16(d[st][1][0], d[st][1][1], d[st][1][2], d[st][1][3],
                            a0, a1, a2, a3, bb2, bb3);
                }
            }
        }
    }

    // ---- epilogue: out[m,n] = d_m*acc + d_m^2*h[m,n] ----
    #pragma unroll
    for (int st = 0; st < 7; st++) {
        if (st < ns) {
            const int m = grow0 + st * 16 + gid;       // rows m and m+8
            const float dm0 = g_dinv[m];
            const float dm1 = g_dinv[m + 8];
            const float* hf0 = g_feat + (size_t)m * OUT_DIM;
            const float* hf1 = hf0 + (size_t)8 * OUT_DIM;
            float* op0 = out + (size_t)m * OUT_DIM;
            float* op1 = op0 + (size_t)8 * OUT_DIM;
            #pragma unroll
            for (int nt = 0; nt < 2; nt++) {
                const int n = wid * 16 + nt * 8 + 2 * tig;
                float2 hv0 = *reinterpret_cast<const float2*>(hf0 + n);
                float2 hv1 = *reinterpret_cast<const float2*>(hf1 + n);
                float2 o0, o1;
                o0.x = dm0 * (d[st][nt][0] + dm0 * hv0.x);
                o0.y = dm0 * (d[st][nt][1] + dm0 * hv0.y);
                o1.x = dm1 * (d[st][nt][2] + dm1 * hv1.x);
                o1.y = dm1 * (d[st][nt][3] + dm1 * hv1.y);
                *reinterpret_cast<float2*>(op0 + n) = o0;
                *reinterpret_cast<float2*>(op1 + n) = o1;
            }
        }
    }
}

// ---------------------------------------------------------------------------
extern "C" void kernel_launch(void* const* d_in, const int* in_sizes, int n_in,
                              void* d_out, int out_size) {
    const float* x = (const float*)d_in[0];   // [16384, 512]
    const float* A = (const float*)d_in[1];   // [16384, 16384]
    const float* W = (const float*)d_in[2];   // [256, 512]
    const float* b = (const float*)d_in[3];   // [256]
    float* out = (float*)d_out;               // [16384, 256]

    cudaFuncSetAttribute(agg_kernel, cudaFuncAttributeMaxDynamicSharedMemorySize, AGG_SMEM);

    prep_kernel<<<LIN_BLOCKS + N_NODES, 256>>>(A, x, W, b);
    scaleB_kernel<<<(OUT_DIM * N_NODES / 8) / 256, 256>>>();
    agg_kernel<<<148, 512, AGG_SMEM>>>(out);
}